// round 12
// baseline (speedup 1.0000x reference)
#include <cuda_runtime.h>
#include <cuda_bf16.h>
#include <math.h>
#include <stdint.h>

// Problem constants
#define Bn 4
#define FC 64
#define TC 64
#define HID 48
#define HR 2
#define Gg 8
#define Hc 128
#define Wc 256
#define Dd 5
#define CG 8
#define GRU_IN 236
#define HCTX 108
#define HW (Hc*Wc)            // 32768
#define NPIX (Bn*HW)          // 131072

// Output layout (flattened tuple in return order)
#define O_D    0
#define O_SX   (NPIX)
#define O_SY   (2*NPIX)
#define O_H    (3*NPIX)
#define O_CONF (3*NPIX + Bn*TC*HW)

// Scratch (device globals; no allocation allowed)
__device__ float g_hctx[(size_t)Bn*HCTX*HW];     // [fR_w(64), d,sx,sy,conf(4), cost(40)]
__device__ float g_z  [(size_t)Bn*TC*HW];
__device__ float g_r  [(size_t)Bn*TC*HW];        // holds r*feat (fused)
__device__ float g_hnew[(size_t)Bn*TC*HW];
__device__ float g_ta [(size_t)Bn*HID*HW];       // trunk1 raw output
__device__ float g_tb [(size_t)Bn*HID*HW];       // trunk2 raw output
__device__ float g_gnsum[128];                   // 2 sets x 32 (b,g) x {sum,sum2}

// Fragment-permuted tf32 weights: [chunk][tap][ocq][lane] -> float2 {b0,b1}
__device__ float2 g_wzr[30*9*16*32];   // z|r fused, OC=128
__device__ float2 g_wq [30*9* 8*32];   // q, OC=64
__device__ float2 g_wt1[ 8*9* 6*32];   // trunk1, IC=64, OC=48
__device__ float2 g_wt2[ 6*9* 6*32];   // trunk2, IC=48, OC=48

#define GN_N ((HID/Gg)*HW)     // elements per (b,group) = 196608

// ---- fast transcendentals (MUFU-based) ----
__device__ __forceinline__ float fsig(float x){
    return __fdividef(1.0f, 1.0f + __expf(-x));
}
__device__ __forceinline__ float ftanh(float x){
    float xc = fminf(fmaxf(x, -15.0f), 15.0f);
    float e  = __expf(2.0f*xc);
    return __fdividef(e - 1.0f, e + 1.0f);
}
__device__ __forceinline__ float fsoftplus(float x){
    return (x > 20.0f) ? x : __logf(1.0f + __expf(x));
}

__device__ __forceinline__ unsigned to_tf32(float v) {
    unsigned u;
    asm("cvt.rna.tf32.f32 %0, %1;" : "=r"(u) : "f"(v));
    return u;
}

__device__ __forceinline__ void mma_tf32(float* c, unsigned a0, unsigned a1,
                                         unsigned a2, unsigned a3,
                                         unsigned b0, unsigned b1) {
    asm volatile(
        "mma.sync.aligned.m16n8k8.row.col.f32.tf32.tf32.f32 "
        "{%0,%1,%2,%3}, {%4,%5,%6,%7}, {%8,%9}, {%0,%1,%2,%3};"
        : "+f"(c[0]), "+f"(c[1]), "+f"(c[2]), "+f"(c[3])
        : "r"(a0), "r"(a1), "r"(a2), "r"(a3), "r"(b0), "r"(b1));
}

__device__ __forceinline__ void cp16(uint32_t dst, const void* src, int szbytes){
    asm volatile("cp.async.cg.shared.global [%0], [%1], 16, %2;"
                 :: "r"(dst), "l"(src), "r"(szbytes));
}
__device__ __forceinline__ void cp_commit(){ asm volatile("cp.async.commit_group;"); }
__device__ __forceinline__ void cp_wait_all(){ asm volatile("cp.async.wait_all;" ::: "memory"); }

__device__ __forceinline__ void gn_mr(int set, int bg, float& mean, float& rstd)
{
    float s  = g_gnsum[set*64 + bg*2];
    float s2 = g_gnsum[set*64 + bg*2 + 1];
    mean = s * (1.0f/(float)GN_N);
    float var = s2 * (1.0f/(float)GN_N) - mean*mean;
    rstd = rsqrtf(var + 1e-5f);
}

// ---------------------------------------------------------------------------
// K0: ALL weight permutes in one launch + zero gn accumulator.
// ---------------------------------------------------------------------------
__device__ __forceinline__ void wperm_one(const float* wA, const float* wB,
                                          float2* dst, int IC, int OC, int i)
{
    int lane = i & 31;
    int t1   = i >> 5;
    int ocq  = t1 % (OC/8);
    int rest = t1 / (OC/8);
    int tap  = rest % 9;
    int chunk= rest / 9;
    int gID = lane >> 2, tig = lane & 3;
    int oc  = ocq*8 + gID;
    int ic0 = chunk*8 + tig, ic1 = ic0 + 4;
    const float* wsrc = wA; int oce = oc;
    if (oc >= 64 && wB) { wsrc = wB; oce = oc - 64; }
    float v0 = (ic0 < IC) ? wsrc[((size_t)oce*IC + ic0)*9 + tap] : 0.f;
    float v1 = (ic1 < IC) ? wsrc[((size_t)oce*IC + ic1)*9 + tap] : 0.f;
    dst[i] = make_float2(__uint_as_float(to_tf32(v0)), __uint_as_float(to_tf32(v1)));
}

#define NZR (30*9*16*32)
#define NQ  (30*9*8*32)
#define NT1 (8*9*6*32)
#define NT2 (6*9*6*32)

__global__ void wperm_all_k(const float* __restrict__ wz, const float* __restrict__ wr,
                            const float* __restrict__ wq, const float* __restrict__ w1,
                            const float* __restrict__ w2)
{
    int i = blockIdx.x*blockDim.x + threadIdx.x;
    if (i < 128) g_gnsum[i] = 0.f;
    if (i < NZR) { wperm_one(wz, wr, g_wzr, GRU_IN, 128, i); return; }
    i -= NZR;
    if (i < NQ)  { wperm_one(wq, nullptr, g_wq, GRU_IN, 64, i); return; }
    i -= NQ;
    if (i < NT1) { wperm_one(w1, nullptr, g_wt1, TC, HID, i); return; }
    i -= NT1;
    if (i < NT2) { wperm_one(w2, nullptr, g_wt2, HID, HID, i); return; }
}

// ---------------------------------------------------------------------------
// K1: build hctx108 = [fR_w(64), d, sx, sy, conf, cost(40)]
// 4 threads per pixel: quarter q handles channels q*16 .. q*16+15.
// ---------------------------------------------------------------------------
__global__ void build_hctx_k(const float* __restrict__ d_, const float* __restrict__ sx,
                             const float* __restrict__ sy, const float* __restrict__ conf,
                             const float* __restrict__ fL, const float* __restrict__ fR)
{
    int idx = blockIdx.x*blockDim.x + threadIdx.x;
    if (idx >= 4*NPIX) return;
    int quarter = idx & 3;
    int pixi = idx >> 2;
    int w = pixi & (Wc-1);
    int h = (pixi >> 8) & (Hc-1);
    int b = pixi >> 15;
    size_t p = (size_t)h*Wc + w;
    size_t pix = (size_t)pixi;

    float d0 = d_[pix];

    int i0[Dd], i1[Dd]; float fr[Dd];
#pragma unroll
    for (int o = 0; o < Dd; o++) {
        float xs = (float)w - d0 - (float)(o - HR);
        xs = fminf(fmaxf(xs, 0.0f), (float)(Wc-1));
        float x0f = floorf(xs);
        i0[o] = (int)x0f;
        i1[o] = min(i0[o] + 1, Wc-1);
        fr[o] = xs - x0f;
    }

    size_t hb = (size_t)b * HCTX * HW;
    float cost[Dd] = {0.f,0.f,0.f,0.f,0.f};

    int c0 = quarter*16;
    for (int c = c0; c < c0+16; c++) {
        size_t fbase = ((size_t)(b*FC + c)) * HW;
        float fl = __ldg(fL + fbase + p);
        const float* fRrow = fR + fbase + (size_t)h*Wc;
#pragma unroll
        for (int o = 0; o < Dd; o++) {
            float s = __ldg(fRrow + i0[o])*(1.0f-fr[o]) + __ldg(fRrow + i1[o])*fr[o];
            cost[o] += fl * s;
            if (o == HR) g_hctx[hb + (size_t)c*HW + p] = s;   // fR_w
        }
        if ((c & (CG-1)) == (CG-1)) {
            int g = c >> 3;
#pragma unroll
            for (int o = 0; o < Dd; o++) {
                g_hctx[hb + (size_t)(68 + g*Dd + o)*HW + p] = cost[o] * (1.0f/(float)CG);
                cost[o] = 0.f;
            }
        }
    }
    if (quarter == 0) {
        g_hctx[hb + (size_t)64*HW + p] = d0;
        g_hctx[hb + (size_t)65*HW + p] = sx[pix];
        g_hctx[hb + (size_t)66*HW + p] = sy[pix];
        g_hctx[hb + (size_t)67*HW + p] = conf[pix];
    }
}

// ---------------------------------------------------------------------------
// Tensor-core 3x3 conv (pad=1), implicit GEMM, tf32 mma.
// Inputs cp.async double-buffered in smem (or LDG+norm+SiLU+STS if SNORM);
// weights read as pre-permuted fragments directly from global.
// MODE 0: plain   MODE 2: GRU combine (q)   MODE 4: fused z|r (OC=128)
// GNSET >= 0: accumulate GroupNorm (sum,sum2) of outputs into g_gnsum[GNSET].
// SNORM: staging applies gn set-0 normalize + SiLU to p0 (single source).
// ---------------------------------------------------------------------------
template<int IC, int OC, int THREADS, int MODE, int GNSET, int SNORM>
__global__ void __launch_bounds__(THREADS, (THREADS==512)?1:2)
conv3x3_cp_k(const float* __restrict__ p0, int C0tot,
             const float* __restrict__ p1, int C1tot,
             const float* __restrict__ p2, int C2tot,
             const float2* __restrict__ wperm,
             const float* __restrict__ biasA, const float* __restrict__ biasB,
             const float* __restrict__ nsc, const float* __restrict__ nbi,
             float* __restrict__ out,
             const float* __restrict__ zbuf, const float* __restrict__ featbuf,
             float* __restrict__ out2)
{
    constexpr int NW   = THREADS/32;
    constexpr int OCW  = OC/(NW/4);
    constexpr int NF   = OCW/8;
    constexpr int OC8  = OC/8;
    constexpr int NCHK = (IC + 7)/8;
    constexpr int PI   = 264;            // ism row pitch (words)
    constexpr int IST  = 8*3*PI;         // ism words per stage

    extern __shared__ unsigned dsm[];
    uint32_t smem_b = (uint32_t)__cvta_generic_to_shared(dsm);

    const int tid  = threadIdx.x;
    const int lane = tid & 31;
    const int warp = tid >> 5;
    const int wm   = warp & 3;
    const int wn   = warp >> 2;
    const int h    = blockIdx.x;
    const int b    = blockIdx.y;
    const int gID  = lane >> 2;
    const int tig  = lane & 3;

    float acc[4][NF][4];
#pragma unroll
    for (int mf = 0; mf < 4; mf++)
#pragma unroll
        for (int f = 0; f < NF; f++)
#pragma unroll
            for (int j = 0; j < 4; j++) acc[mf][f][j] = 0.f;

    auto stage = [&](int chunk, int s) {
        if (SNORM) {
            // normalized staging: LDG from p0, apply gn set-0 + SiLU, STS
            for (int t = warp; t < 24; t += NW) {
                int icl = t / 3;
                int ky  = t - icl*3;
                int ic  = chunk*8 + icl;
                int gy  = h - 1 + ky;
                bool valid = (ic < IC) && (gy >= 0) && (gy < Hc);
                unsigned* drow = dsm + s*IST + t*PI;
                if (valid) {
                    int g = ic / (HID/Gg);
                    float mean, rstd; gn_mr(0, b*8+g, mean, rstd);
                    float sv = nsc[ic];
                    float scv = sv*rstd, biv = nbi[ic] - mean*rstd*sv;
                    const float4* srcrow = (const float4*)(p0 + (((size_t)b*C0tot + ic)*Hc + gy)*Wc);
#pragma unroll
                    for (int j = 0; j < 2; j++) {
                        float4 v = __ldg(srcrow + lane + j*32);
                        float t0;
                        t0 = v.x*scv + biv; v.x = t0*fsig(t0);
                        t0 = v.y*scv + biv; v.y = t0*fsig(t0);
                        t0 = v.z*scv + biv; v.z = t0*fsig(t0);
                        t0 = v.w*scv + biv; v.w = t0*fsig(t0);
                        ((float4*)(drow + 4))[lane + j*32] = v;
                    }
                } else {
#pragma unroll
                    for (int j = 0; j < 2; j++)
                        ((float4*)(drow + 4))[lane + j*32] = make_float4(0.f,0.f,0.f,0.f);
                }
                if (lane == 0) drow[3]   = 0u;
                if (lane == 1) drow[260] = 0u;
            }
            return;
        }
        for (int t = warp; t < 24; t += NW) {
            int icl = t / 3;
            int ky  = t - icl*3;
            int ic  = chunk*8 + icl;
            int gy  = h - 1 + ky;
            bool valid = (ic < IC) && (gy >= 0) && (gy < Hc);
            int icc = valid ? ic : 0;
            int gyc = min(max(gy, 0), Hc-1);
            const float* srcrow;
            if (icc < 64)       srcrow = p0 + (((size_t)b*C0tot + icc)*Hc + gyc)*Wc;
            else if (icc < 128) srcrow = p1 + (((size_t)b*C1tot + (icc-64))*Hc + gyc)*Wc;
            else                srcrow = p2 + (((size_t)b*C2tot + (icc-128))*Hc + gyc)*Wc;
            uint32_t dstw = smem_b + ((uint32_t)(s*IST + t*PI))*4u;
            int sz = valid ? 16 : 0;
            cp16(dstw + (4u + (uint32_t)lane*4u)*4u,      srcrow + lane*4,      sz);
            cp16(dstw + (4u + (uint32_t)(lane+32)*4u)*4u, srcrow + (lane+32)*4, sz);
            if (lane == 0) dsm[s*IST + t*PI + 3]   = 0u;   // left pad
            if (lane == 1) dsm[s*IST + t*PI + 260] = 0u;   // right pad
        }
    };

    stage(0, 0);
    cp_commit();

    for (int c = 0; c < NCHK; c++) {
        cp_wait_all();
        __syncthreads();
        if (c + 1 < NCHK) { stage(c+1, (c+1)&1); cp_commit(); }

        const unsigned* isb = dsm + (c&1)*IST;
        const float2* wcb = wperm + ((size_t)(c*9)*OC8)*32;

#pragma unroll
        for (int tap = 0; tap < 9; tap++) {
            const int ky = tap/3, kx = tap - (tap/3)*3;
            const float2* wtb = wcb + ((size_t)tap*OC8 + wn*NF)*32 + lane;
            unsigned b0[NF], b1[NF];
#pragma unroll
            for (int f = 0; f < NF; f++) {
                float2 wv = __ldg(wtb + f*32);
                b0[f] = __float_as_uint(wv.x);
                b1[f] = __float_as_uint(wv.y);
            }
            const unsigned* ib = isb + ky*PI + kx + 3;
#pragma unroll
            for (int mf = 0; mf < 4; mf++) {
                int p = wm*64 + mf*16 + gID;
                unsigned a0 = ib[ tig   *3*PI + p];
                unsigned a1 = ib[ tig   *3*PI + p + 8];
                unsigned a2 = ib[(tig+4)*3*PI + p];
                unsigned a3 = ib[(tig+4)*3*PI + p + 8];
#pragma unroll
                for (int f = 0; f < NF; f++)
                    mma_tf32(acc[mf][f], a0, a1, a2, a3, b0[f], b1[f]);
            }
        }
    }

    // ---- epilogue ----
    float s1l[NF][2];
    float s2l[NF][2];
    if (GNSET >= 0) {
#pragma unroll
        for (int f = 0; f < NF; f++) { s1l[f][0]=0.f; s1l[f][1]=0.f; s2l[f][0]=0.f; s2l[f][1]=0.f; }
    }

#pragma unroll
    for (int mf = 0; mf < 4; mf++) {
#pragma unroll
        for (int f = 0; f < NF; f++) {
            int px0 = wm*64 + mf*16 + gID;
            int oc0 = wn*OCW + f*8 + 2*tig;
#pragma unroll
            for (int e = 0; e < 4; e++) {
                int px = px0 + (e >> 1)*8;
                int oc = oc0 + (e & 1);
                float val = acc[mf][f][e];
                if (MODE == 4) {
                    if (oc < 64) {
                        size_t o = (((size_t)b*64 + oc)*Hc + h)*Wc + px;
                        out[o] = fsig(val + biasA[oc]);
                    } else {
                        int oc2 = oc - 64;
                        size_t o = (((size_t)b*64 + oc2)*Hc + h)*Wc + px;
                        out2[o] = fsig(val + biasB[oc2]) * featbuf[o];
                    }
                } else {
                    size_t o = (((size_t)b*OC + oc)*Hc + h)*Wc + px;
                    if (MODE == 0) {
                        out[o] = val + (biasA ? biasA[oc] : 0.f);
                        if (GNSET >= 0) {
                            s1l[f][e&1] += val;
                            s2l[f][e&1] += val*val;
                        }
                    } else { // MODE 2: GRU combine
                        float q = ftanh(val + biasA[oc]);
                        float z = zbuf[o];
                        float fv = featbuf[o];
                        float hn = (1.0f - z)*fv + z*q;
                        out[o]  = hn;
                        out2[o] = hn;
                    }
                }
            }
        }
    }

    if (GNSET >= 0) {
        __shared__ float gsum[16];
        if (tid < 16) gsum[tid] = 0.f;
        __syncthreads();
#pragma unroll
        for (int f = 0; f < NF; f++) {
#pragma unroll
            for (int par = 0; par < 2; par++) {
                float a  = s1l[f][par];
                float b2 = s2l[f][par];
                a  += __shfl_xor_sync(0xffffffffu, a, 4);
                b2 += __shfl_xor_sync(0xffffffffu, b2, 4);
                a  += __shfl_xor_sync(0xffffffffu, a, 8);
                b2 += __shfl_xor_sync(0xffffffffu, b2, 8);
                a  += __shfl_xor_sync(0xffffffffu, a, 16);
                b2 += __shfl_xor_sync(0xffffffffu, b2, 16);
                if (gID == 0) {
                    int oc = wn*OCW + f*8 + 2*tig + par;
                    int g  = oc / (HID/Gg);
                    atomicAdd(&gsum[g*2],     a);
                    atomicAdd(&gsum[g*2 + 1], b2);
                }
            }
        }
        __syncthreads();
        if (tid < 16) atomicAdd(&g_gnsum[GNSET*64 + b*16 + tid], gsum[tid]);
    }
}

// ---------------------------------------------------------------------------
// Heads: fused GN2-apply + SiLU + four 1x1 convs (48->1) + activations.
// ---------------------------------------------------------------------------
__global__ void heads_k(const float* __restrict__ t,
                        const float* __restrict__ gnsc, const float* __restrict__ gnbi,
                        const float* __restrict__ d_, const float* __restrict__ sx,
                        const float* __restrict__ sy, const float* __restrict__ conf,
                        const float* __restrict__ wd,  const float* __restrict__ bd,
                        const float* __restrict__ wsx, const float* __restrict__ bsx,
                        const float* __restrict__ wsy, const float* __restrict__ bsy,
                        const float* __restrict__ wcf, const float* __restrict__ bcf,
                        float* __restrict__ out)
{
    __shared__ float wsm[4][HID];
    __shared__ float csc[HID], cbi[HID];
    int tid = threadIdx.x;
    if (tid < HID)              wsm[0][tid]        = wd [tid];
    else if (tid < 2*HID)       wsm[1][tid-HID]    = wsx[tid-HID];
    else if (tid < 3*HID)       wsm[2][tid-2*HID]  = wsy[tid-2*HID];
    else if (tid < 4*HID)       wsm[3][tid-3*HID]  = wcf[tid-3*HID];
    if (tid < HID) { csc[tid] = gnsc[tid]; cbi[tid] = gnbi[tid]; }
    __syncthreads();

    int idx = blockIdx.x*blockDim.x + tid;
    if (idx >= NPIX) return;
    int b = idx >> 15;
    size_t p = (size_t)(idx & (HW-1));
    size_t pix = (size_t)idx;

    float gmean[8], grstd[8];
#pragma unroll
    for (int g = 0; g < 8; g++) gn_mr(1, b*8+g, gmean[g], grstd[g]);

    float a0=0.f, a1=0.f, a2=0.f, a3=0.f;
    size_t base = (size_t)b*HID*HW + p;
#pragma unroll
    for (int c = 0; c < HID; c++) {
        int g = c / (HID/Gg);
        float v = (t[base + (size_t)c*HW] - gmean[g])*grstd[g]*csc[c] + cbi[c];
        v = v * fsig(v);
        a0 = fmaf(v, wsm[0][c], a0);
        a1 = fmaf(v, wsm[1][c], a1);
        a2 = fmaf(v, wsm[2][c], a2);
        a3 = fmaf(v, wsm[3][c], a3);
    }
    float ad = a0 + bd[0] + d_[pix];
    out[O_D + pix]  = fsoftplus(ad);
    out[O_SX + pix] = sx[pix] + (a1 + bsx[0]) * 0.1f;
    out[O_SY + pix] = sy[pix] + (a2 + bsy[0]) * 0.1f;
    out[O_CONF + pix] = fsig(a3 + bcf[0] + 2.0f*conf[pix] - 1.0f);
}

// ---------------------------------------------------------------------------
extern "C" void kernel_launch(void* const* d_in, const int* in_sizes, int n_in,
                              void* d_out, int out_size)
{
    const float* d_   = (const float*)d_in[0];
    const float* sx   = (const float*)d_in[1];
    const float* sy   = (const float*)d_in[2];
    const float* conf = (const float*)d_in[3];
    const float* feat = (const float*)d_in[4];
    const float* fL   = (const float*)d_in[5];
    const float* fR   = (const float*)d_in[6];
    const float* wz   = (const float*)d_in[7];
    const float* bz   = (const float*)d_in[8];
    const float* wr   = (const float*)d_in[9];
    const float* br   = (const float*)d_in[10];
    const float* wq   = (const float*)d_in[11];
    const float* bq   = (const float*)d_in[12];
    const float* w1   = (const float*)d_in[13];
    const float* g1s  = (const float*)d_in[14];
    const float* g1b  = (const float*)d_in[15];
    const float* w2   = (const float*)d_in[16];
    const float* g2s  = (const float*)d_in[17];
    const float* g2b  = (const float*)d_in[18];
    const float* whd  = (const float*)d_in[19];
    const float* bhd  = (const float*)d_in[20];
    const float* whx  = (const float*)d_in[21];
    const float* bhx  = (const float*)d_in[22];
    const float* why  = (const float*)d_in[23];
    const float* bhy  = (const float*)d_in[24];
    const float* whc  = (const float*)d_in[25];
    const float* bhc  = (const float*)d_in[26];
    float* out = (float*)d_out;

    float *hctx, *z, *r, *hnew, *ta, *tb;
    float2 *wzr, *wqp, *wt1, *wt2;
    cudaGetSymbolAddress((void**)&hctx, g_hctx);
    cudaGetSymbolAddress((void**)&z,    g_z);
    cudaGetSymbolAddress((void**)&r,    g_r);
    cudaGetSymbolAddress((void**)&hnew, g_hnew);
    cudaGetSymbolAddress((void**)&ta,   g_ta);
    cudaGetSymbolAddress((void**)&tb,   g_tb);
    cudaGetSymbolAddress((void**)&wzr,  g_wzr);
    cudaGetSymbolAddress((void**)&wqp,  g_wq);
    cudaGetSymbolAddress((void**)&wt1,  g_wt1);
    cudaGetSymbolAddress((void**)&wt2,  g_wt2);

    const int SM_I = 2*(8*3*264)*4;     // 50688 bytes (2 input stages)

    cudaFuncSetAttribute(conv3x3_cp_k<GRU_IN,128,512,4,-1,0>,
                         cudaFuncAttributeMaxDynamicSharedMemorySize, SM_I);
    cudaFuncSetAttribute(conv3x3_cp_k<GRU_IN,64,256,2,-1,0>,
                         cudaFuncAttributeMaxDynamicSharedMemorySize, SM_I);
    cudaFuncSetAttribute(conv3x3_cp_k<TC,HID,256,0,0,0>,
                         cudaFuncAttributeMaxDynamicSharedMemorySize, SM_I);
    cudaFuncSetAttribute(conv3x3_cp_k<HID,HID,256,0,1,1>,
                         cudaFuncAttributeMaxDynamicSharedMemorySize, SM_I);

    // One-time weight permutes + gnsum zero (single launch)
    {
        int total = NZR + NQ + NT1 + NT2;
        wperm_all_k<<<(total+255)/256, 256>>>(wz, wr, wq, w1, w2);
    }

    dim3 cgrid(Hc, Bn);

    build_hctx_k<<<(4*NPIX)/256, 256>>>(d_, sx, sy, conf, fL, fR);

    // fused z|r conv: z = sigmoid(conv_z); r*feat = sigmoid(conv_r)*feat
    conv3x3_cp_k<GRU_IN,128,512,4,-1,0><<<cgrid, 512, SM_I>>>(
        feat, 64, fL, 64, hctx, HCTX,
        wzr, bz, br, nullptr, nullptr, z, nullptr, feat, r);

    // q conv + GRU combine -> hnew (and output h slot)
    conv3x3_cp_k<GRU_IN,64,256,2,-1,0><<<cgrid, 256, SM_I>>>(
        r, 64, fL, 64, hctx, HCTX,
        wqp, bq, nullptr, nullptr, nullptr, hnew, z, feat, out + O_H);

    // trunk1: conv(hnew) -> ta, with fused GN set-0 stats
    conv3x3_cp_k<TC,HID,256,0,0,0><<<cgrid, 256, SM_I>>>(
        hnew, TC, hnew, TC, hnew, TC,
        wt1, nullptr, nullptr, nullptr, nullptr, ta, nullptr, nullptr, nullptr);

    // trunk2: staging applies gn1+SiLU to ta; conv -> tb, fused GN set-1 stats
    conv3x3_cp_k<HID,HID,256,0,1,1><<<cgrid, 256, SM_I>>>(
        ta, HID, ta, HID, ta, HID,
        wt2, nullptr, nullptr, g1s, g1b, tb, nullptr, nullptr, nullptr);

    // heads with fused GN2 apply + SiLU
    heads_k<<<NPIX/256, 256>>>(tb, g2s, g2b, d_, sx, sy, conf,
                               whd, bhd, whx, bhx, why, bhy, whc, bhc, out);
}

// round 13
// speedup vs baseline: 1.0068x; 1.0068x over previous
#include <cuda_runtime.h>
#include <cuda_bf16.h>
#include <math.h>
#include <stdint.h>

// Problem constants
#define Bn 4
#define FC 64
#define TC 64
#define HID 48
#define HR 2
#define Gg 8
#define Hc 128
#define Wc 256
#define Dd 5
#define CG 8
#define GRU_IN 236
#define HCTX 108
#define HW (Hc*Wc)            // 32768
#define NPIX (Bn*HW)          // 131072

// Output layout (flattened tuple in return order)
#define O_D    0
#define O_SX   (NPIX)
#define O_SY   (2*NPIX)
#define O_H    (3*NPIX)
#define O_CONF (3*NPIX + Bn*TC*HW)

// Scratch (device globals; no allocation allowed)
__device__ float g_hctx[(size_t)Bn*HCTX*HW];     // [fR_w(64), d,sx,sy,conf(4), cost(40)]
__device__ float g_z  [(size_t)Bn*TC*HW];
__device__ float g_r  [(size_t)Bn*TC*HW];        // holds r*feat (fused)
__device__ float g_hnew[(size_t)Bn*TC*HW];
__device__ float g_ta [(size_t)Bn*HID*HW];       // trunk1 raw output
__device__ float g_tb [(size_t)Bn*HID*HW];       // gn1(ta) then trunk2 raw output (separate halves of flow)
__device__ float g_tc [(size_t)Bn*HID*HW];       // trunk2 raw output
__device__ float g_gnsum[128];                   // 2 sets x 32 (b,g) x {sum,sum2}

// Fragment-permuted tf32 weights: [chunk][tap][ocq][lane] -> float2 {b0,b1}
__device__ float2 g_wzr[30*9*16*32];   // z|r fused, OC=128
__device__ float2 g_wq [30*9* 8*32];   // q, OC=64
__device__ float2 g_wt1[ 8*9* 6*32];   // trunk1, IC=64, OC=48
__device__ float2 g_wt2[ 6*9* 6*32];   // trunk2, IC=48, OC=48

#define GN_N ((HID/Gg)*HW)     // elements per (b,group) = 196608

// ---- fast transcendentals (MUFU-based) ----
__device__ __forceinline__ float fsig(float x){
    return __fdividef(1.0f, 1.0f + __expf(-x));
}
__device__ __forceinline__ float ftanh(float x){
    float xc = fminf(fmaxf(x, -15.0f), 15.0f);
    float e  = __expf(2.0f*xc);
    return __fdividef(e - 1.0f, e + 1.0f);
}
__device__ __forceinline__ float fsoftplus(float x){
    return (x > 20.0f) ? x : __logf(1.0f + __expf(x));
}

__device__ __forceinline__ unsigned to_tf32(float v) {
    unsigned u;
    asm("cvt.rna.tf32.f32 %0, %1;" : "=r"(u) : "f"(v));
    return u;
}

__device__ __forceinline__ void mma_tf32(float* c, unsigned a0, unsigned a1,
                                         unsigned a2, unsigned a3,
                                         unsigned b0, unsigned b1) {
    asm volatile(
        "mma.sync.aligned.m16n8k8.row.col.f32.tf32.tf32.f32 "
        "{%0,%1,%2,%3}, {%4,%5,%6,%7}, {%8,%9}, {%0,%1,%2,%3};"
        : "+f"(c[0]), "+f"(c[1]), "+f"(c[2]), "+f"(c[3])
        : "r"(a0), "r"(a1), "r"(a2), "r"(a3), "r"(b0), "r"(b1));
}

__device__ __forceinline__ void cp16(uint32_t dst, const void* src, int szbytes){
    asm volatile("cp.async.cg.shared.global [%0], [%1], 16, %2;"
                 :: "r"(dst), "l"(src), "r"(szbytes));
}
__device__ __forceinline__ void cp_commit(){ asm volatile("cp.async.commit_group;"); }
__device__ __forceinline__ void cp_wait_all(){ asm volatile("cp.async.wait_all;" ::: "memory"); }

__device__ __forceinline__ void gn_mr(int set, int bg, float& mean, float& rstd)
{
    float s  = g_gnsum[set*64 + bg*2];
    float s2 = g_gnsum[set*64 + bg*2 + 1];
    mean = s * (1.0f/(float)GN_N);
    float var = s2 * (1.0f/(float)GN_N) - mean*mean;
    rstd = rsqrtf(var + 1e-5f);
}

// ---------------------------------------------------------------------------
// K0: ALL weight permutes in one launch + zero gn accumulator.
// ---------------------------------------------------------------------------
__device__ __forceinline__ void wperm_one(const float* wA, const float* wB,
                                          float2* dst, int IC, int OC, int i)
{
    int lane = i & 31;
    int t1   = i >> 5;
    int ocq  = t1 % (OC/8);
    int rest = t1 / (OC/8);
    int tap  = rest % 9;
    int chunk= rest / 9;
    int gID = lane >> 2, tig = lane & 3;
    int oc  = ocq*8 + gID;
    int ic0 = chunk*8 + tig, ic1 = ic0 + 4;
    const float* wsrc = wA; int oce = oc;
    if (oc >= 64 && wB) { wsrc = wB; oce = oc - 64; }
    float v0 = (ic0 < IC) ? wsrc[((size_t)oce*IC + ic0)*9 + tap] : 0.f;
    float v1 = (ic1 < IC) ? wsrc[((size_t)oce*IC + ic1)*9 + tap] : 0.f;
    dst[i] = make_float2(__uint_as_float(to_tf32(v0)), __uint_as_float(to_tf32(v1)));
}

#define NZR (30*9*16*32)
#define NQ  (30*9*8*32)
#define NT1 (8*9*6*32)
#define NT2 (6*9*6*32)

__global__ void wperm_all_k(const float* __restrict__ wz, const float* __restrict__ wr,
                            const float* __restrict__ wq, const float* __restrict__ w1,
                            const float* __restrict__ w2)
{
    int i = blockIdx.x*blockDim.x + threadIdx.x;
    if (i < 128) g_gnsum[i] = 0.f;
    if (i < NZR) { wperm_one(wz, wr, g_wzr, GRU_IN, 128, i); return; }
    i -= NZR;
    if (i < NQ)  { wperm_one(wq, nullptr, g_wq, GRU_IN, 64, i); return; }
    i -= NQ;
    if (i < NT1) { wperm_one(w1, nullptr, g_wt1, TC, HID, i); return; }
    i -= NT1;
    if (i < NT2) { wperm_one(w2, nullptr, g_wt2, HID, HID, i); return; }
}

// ---------------------------------------------------------------------------
// K1: build hctx108 = [fR_w(64), d, sx, sy, conf, cost(40)]
// 4 threads per pixel: quarter q handles channels q*16 .. q*16+15.
// ---------------------------------------------------------------------------
__global__ void build_hctx_k(const float* __restrict__ d_, const float* __restrict__ sx,
                             const float* __restrict__ sy, const float* __restrict__ conf,
                             const float* __restrict__ fL, const float* __restrict__ fR)
{
    int idx = blockIdx.x*blockDim.x + threadIdx.x;
    if (idx >= 4*NPIX) return;
    int quarter = idx & 3;
    int pixi = idx >> 2;
    int w = pixi & (Wc-1);
    int h = (pixi >> 8) & (Hc-1);
    int b = pixi >> 15;
    size_t p = (size_t)h*Wc + w;
    size_t pix = (size_t)pixi;

    float d0 = d_[pix];

    int i0[Dd], i1[Dd]; float fr[Dd];
#pragma unroll
    for (int o = 0; o < Dd; o++) {
        float xs = (float)w - d0 - (float)(o - HR);
        xs = fminf(fmaxf(xs, 0.0f), (float)(Wc-1));
        float x0f = floorf(xs);
        i0[o] = (int)x0f;
        i1[o] = min(i0[o] + 1, Wc-1);
        fr[o] = xs - x0f;
    }

    size_t hb = (size_t)b * HCTX * HW;
    float cost[Dd] = {0.f,0.f,0.f,0.f,0.f};

    int c0 = quarter*16;
    for (int c = c0; c < c0+16; c++) {
        size_t fbase = ((size_t)(b*FC + c)) * HW;
        float fl = __ldg(fL + fbase + p);
        const float* fRrow = fR + fbase + (size_t)h*Wc;
#pragma unroll
        for (int o = 0; o < Dd; o++) {
            float s = __ldg(fRrow + i0[o])*(1.0f-fr[o]) + __ldg(fRrow + i1[o])*fr[o];
            cost[o] += fl * s;
            if (o == HR) g_hctx[hb + (size_t)c*HW + p] = s;   // fR_w
        }
        if ((c & (CG-1)) == (CG-1)) {
            int g = c >> 3;
#pragma unroll
            for (int o = 0; o < Dd; o++) {
                g_hctx[hb + (size_t)(68 + g*Dd + o)*HW + p] = cost[o] * (1.0f/(float)CG);
                cost[o] = 0.f;
            }
        }
    }
    if (quarter == 0) {
        g_hctx[hb + (size_t)64*HW + p] = d0;
        g_hctx[hb + (size_t)65*HW + p] = sx[pix];
        g_hctx[hb + (size_t)66*HW + p] = sy[pix];
        g_hctx[hb + (size_t)67*HW + p] = conf[pix];
    }
}

// ---------------------------------------------------------------------------
// Tensor-core 3x3 conv (pad=1), implicit GEMM, tf32 mma.
// Inputs cp.async double-buffered in smem; weights read as pre-permuted
// fragments directly from global (L1/L2-resident, coalesced float2).
// MODE 0: plain   MODE 2: GRU combine (q)   MODE 4: fused z|r (OC=128)
// GNSET >= 0: accumulate GroupNorm (sum,sum2) of outputs into g_gnsum[GNSET].
// ---------------------------------------------------------------------------
template<int IC, int OC, int THREADS, int MODE, int GNSET>
__global__ void __launch_bounds__(THREADS, (THREADS==512)?1:2)
conv3x3_cp_k(const float* __restrict__ p0, int C0tot,
             const float* __restrict__ p1, int C1tot,
             const float* __restrict__ p2, int C2tot,
             const float2* __restrict__ wperm,
             const float* __restrict__ biasA, const float* __restrict__ biasB,
             float* __restrict__ out,
             const float* __restrict__ zbuf, const float* __restrict__ featbuf,
             float* __restrict__ out2)
{
    constexpr int NW   = THREADS/32;
    constexpr int OCW  = OC/(NW/4);
    constexpr int NF   = OCW/8;
    constexpr int OC8  = OC/8;
    constexpr int NCHK = (IC + 7)/8;
    constexpr int PI   = 264;            // ism row pitch (words)
    constexpr int IST  = 8*3*PI;         // ism words per stage

    extern __shared__ unsigned dsm[];
    uint32_t smem_b = (uint32_t)__cvta_generic_to_shared(dsm);

    const int tid  = threadIdx.x;
    const int lane = tid & 31;
    const int warp = tid >> 5;
    const int wm   = warp & 3;
    const int wn   = warp >> 2;
    const int h    = blockIdx.x;
    const int b    = blockIdx.y;
    const int gID  = lane >> 2;
    const int tig  = lane & 3;

    float acc[4][NF][4];
#pragma unroll
    for (int mf = 0; mf < 4; mf++)
#pragma unroll
        for (int f = 0; f < NF; f++)
#pragma unroll
            for (int j = 0; j < 4; j++) acc[mf][f][j] = 0.f;

    auto stage = [&](int chunk, int s) {
        for (int t = warp; t < 24; t += NW) {
            int icl = t / 3;
            int ky  = t - icl*3;
            int ic  = chunk*8 + icl;
            int gy  = h - 1 + ky;
            bool valid = (ic < IC) && (gy >= 0) && (gy < Hc);
            int icc = valid ? ic : 0;
            int gyc = min(max(gy, 0), Hc-1);
            const float* srcrow;
            if (icc < 64)       srcrow = p0 + (((size_t)b*C0tot + icc)*Hc + gyc)*Wc;
            else if (icc < 128) srcrow = p1 + (((size_t)b*C1tot + (icc-64))*Hc + gyc)*Wc;
            else                srcrow = p2 + (((size_t)b*C2tot + (icc-128))*Hc + gyc)*Wc;
            uint32_t dstw = smem_b + ((uint32_t)(s*IST + t*PI))*4u;
            int sz = valid ? 16 : 0;
            cp16(dstw + (4u + (uint32_t)lane*4u)*4u,      srcrow + lane*4,      sz);
            cp16(dstw + (4u + (uint32_t)(lane+32)*4u)*4u, srcrow + (lane+32)*4, sz);
            if (lane == 0) dsm[s*IST + t*PI + 3]   = 0u;   // left pad
            if (lane == 1) dsm[s*IST + t*PI + 260] = 0u;   // right pad
        }
    };

    stage(0, 0);
    cp_commit();

    for (int c = 0; c < NCHK; c++) {
        cp_wait_all();
        __syncthreads();
        if (c + 1 < NCHK) { stage(c+1, (c+1)&1); cp_commit(); }

        const unsigned* isb = dsm + (c&1)*IST;
        const float2* wcb = wperm + ((size_t)(c*9)*OC8)*32;

#pragma unroll
        for (int tap = 0; tap < 9; tap++) {
            const int ky = tap/3, kx = tap - (tap/3)*3;
            const float2* wtb = wcb + ((size_t)tap*OC8 + wn*NF)*32 + lane;
            unsigned b0[NF], b1[NF];
#pragma unroll
            for (int f = 0; f < NF; f++) {
                float2 wv = __ldg(wtb + f*32);
                b0[f] = __float_as_uint(wv.x);
                b1[f] = __float_as_uint(wv.y);
            }
            const unsigned* ib = isb + ky*PI + kx + 3;
#pragma unroll
            for (int mf = 0; mf < 4; mf++) {
                int p = wm*64 + mf*16 + gID;
                unsigned a0 = ib[ tig   *3*PI + p];
                unsigned a1 = ib[ tig   *3*PI + p + 8];
                unsigned a2 = ib[(tig+4)*3*PI + p];
                unsigned a3 = ib[(tig+4)*3*PI + p + 8];
#pragma unroll
                for (int f = 0; f < NF; f++)
                    mma_tf32(acc[mf][f], a0, a1, a2, a3, b0[f], b1[f]);
            }
        }
    }

    // ---- epilogue ----
    float s1l[NF][2];
    float s2l[NF][2];
    if (GNSET >= 0) {
#pragma unroll
        for (int f = 0; f < NF; f++) { s1l[f][0]=0.f; s1l[f][1]=0.f; s2l[f][0]=0.f; s2l[f][1]=0.f; }
    }

#pragma unroll
    for (int mf = 0; mf < 4; mf++) {
#pragma unroll
        for (int f = 0; f < NF; f++) {
            int px0 = wm*64 + mf*16 + gID;
            int oc0 = wn*OCW + f*8 + 2*tig;
#pragma unroll
            for (int e = 0; e < 4; e++) {
                int px = px0 + (e >> 1)*8;
                int oc = oc0 + (e & 1);
                float val = acc[mf][f][e];
                if (MODE == 4) {
                    if (oc < 64) {
                        size_t o = (((size_t)b*64 + oc)*Hc + h)*Wc + px;
                        out[o] = fsig(val + biasA[oc]);
                    } else {
                        int oc2 = oc - 64;
                        size_t o = (((size_t)b*64 + oc2)*Hc + h)*Wc + px;
                        out2[o] = fsig(val + biasB[oc2]) * featbuf[o];
                    }
                } else {
                    size_t o = (((size_t)b*OC + oc)*Hc + h)*Wc + px;
                    if (MODE == 0) {
                        out[o] = val + (biasA ? biasA[oc] : 0.f);
                        if (GNSET >= 0) {
                            s1l[f][e&1] += val;
                            s2l[f][e&1] += val*val;
                        }
                    } else { // MODE 2: GRU combine
                        float q = ftanh(val + biasA[oc]);
                        float z = zbuf[o];
                        float fv = featbuf[o];
                        float hn = (1.0f - z)*fv + z*q;
                        out[o]  = hn;
                        out2[o] = hn;
                    }
                }
            }
        }
    }

    if (GNSET >= 0) {
        __shared__ float gsum[16];
        if (tid < 16) gsum[tid] = 0.f;
        __syncthreads();
#pragma unroll
        for (int f = 0; f < NF; f++) {
#pragma unroll
            for (int par = 0; par < 2; par++) {
                float a  = s1l[f][par];
                float b2 = s2l[f][par];
                a  += __shfl_xor_sync(0xffffffffu, a, 4);
                b2 += __shfl_xor_sync(0xffffffffu, b2, 4);
                a  += __shfl_xor_sync(0xffffffffu, a, 8);
                b2 += __shfl_xor_sync(0xffffffffu, b2, 8);
                a  += __shfl_xor_sync(0xffffffffu, a, 16);
                b2 += __shfl_xor_sync(0xffffffffu, b2, 16);
                if (gID == 0) {
                    int oc = wn*OCW + f*8 + 2*tig + par;
                    int g  = oc / (HID/Gg);
                    atomicAdd(&gsum[g*2],     a);
                    atomicAdd(&gsum[g*2 + 1], b2);
                }
            }
        }
        __syncthreads();
        if (tid < 16) atomicAdd(&g_gnsum[GNSET*64 + b*16 + tid], gsum[tid]);
    }
}

// ---------------------------------------------------------------------------
// GroupNorm apply + SiLU (float4)
// ---------------------------------------------------------------------------
__global__ void gn_apply_k(const float* __restrict__ x, float* __restrict__ y,
                           const float* __restrict__ scale, const float* __restrict__ bias,
                           int set)
{
    int i4 = blockIdx.x*blockDim.x + threadIdx.x;
    const int n4 = (Bn*HID*HW)/4;
    if (i4 >= n4) return;
    int i = i4*4;
    int c = (i / HW) % HID;
    int b = i / (HID*HW);
    int grp = c / (HID/Gg);
    float mean, rstd;
    gn_mr(set, b*8+grp, mean, rstd);
    float sc = scale[c]*rstd, bi = bias[c] - mean*rstd*scale[c];
    float4 v = ((const float4*)x)[i4];
    float4 o;
    float t;
    t = v.x*sc + bi; o.x = t * fsig(t);
    t = v.y*sc + bi; o.y = t * fsig(t);
    t = v.z*sc + bi; o.z = t * fsig(t);
    t = v.w*sc + bi; o.w = t * fsig(t);
    ((float4*)y)[i4] = o;
}

// ---------------------------------------------------------------------------
// Heads: fused GN2-apply + SiLU + four 1x1 convs (48->1) + activations.
// ---------------------------------------------------------------------------
__global__ void heads_k(const float* __restrict__ t,
                        const float* __restrict__ gnsc, const float* __restrict__ gnbi,
                        const float* __restrict__ d_, const float* __restrict__ sx,
                        const float* __restrict__ sy, const float* __restrict__ conf,
                        const float* __restrict__ wd,  const float* __restrict__ bd,
                        const float* __restrict__ wsx, const float* __restrict__ bsx,
                        const float* __restrict__ wsy, const float* __restrict__ bsy,
                        const float* __restrict__ wcf, const float* __restrict__ bcf,
                        float* __restrict__ out)
{
    __shared__ float wsm[4][HID];
    __shared__ float csc[HID], cbi[HID];
    int tid = threadIdx.x;
    if (tid < HID)              wsm[0][tid]        = wd [tid];
    else if (tid < 2*HID)       wsm[1][tid-HID]    = wsx[tid-HID];
    else if (tid < 3*HID)       wsm[2][tid-2*HID]  = wsy[tid-2*HID];
    else if (tid < 4*HID)       wsm[3][tid-3*HID]  = wcf[tid-3*HID];
    if (tid < HID) { csc[tid] = gnsc[tid]; cbi[tid] = gnbi[tid]; }
    __syncthreads();

    int idx = blockIdx.x*blockDim.x + tid;
    if (idx >= NPIX) return;
    int b = idx >> 15;
    size_t p = (size_t)(idx & (HW-1));
    size_t pix = (size_t)idx;

    float gmean[8], grstd[8];
#pragma unroll
    for (int g = 0; g < 8; g++) gn_mr(1, b*8+g, gmean[g], grstd[g]);

    float a0=0.f, a1=0.f, a2=0.f, a3=0.f;
    size_t base = (size_t)b*HID*HW + p;
#pragma unroll
    for (int c = 0; c < HID; c++) {
        int g = c / (HID/Gg);
        float v = (t[base + (size_t)c*HW] - gmean[g])*grstd[g]*csc[c] + cbi[c];
        v = v * fsig(v);
        a0 = fmaf(v, wsm[0][c], a0);
        a1 = fmaf(v, wsm[1][c], a1);
        a2 = fmaf(v, wsm[2][c], a2);
        a3 = fmaf(v, wsm[3][c], a3);
    }
    float ad = a0 + bd[0] + d_[pix];
    out[O_D + pix]  = fsoftplus(ad);
    out[O_SX + pix] = sx[pix] + (a1 + bsx[0]) * 0.1f;
    out[O_SY + pix] = sy[pix] + (a2 + bsy[0]) * 0.1f;
    out[O_CONF + pix] = fsig(a3 + bcf[0] + 2.0f*conf[pix] - 1.0f);
}

// ---------------------------------------------------------------------------
extern "C" void kernel_launch(void* const* d_in, const int* in_sizes, int n_in,
                              void* d_out, int out_size)
{
    const float* d_   = (const float*)d_in[0];
    const float* sx   = (const float*)d_in[1];
    const float* sy   = (const float*)d_in[2];
    const float* conf = (const float*)d_in[3];
    const float* feat = (const float*)d_in[4];
    const float* fL   = (const float*)d_in[5];
    const float* fR   = (const float*)d_in[6];
    const float* wz   = (const float*)d_in[7];
    const float* bz   = (const float*)d_in[8];
    const float* wr   = (const float*)d_in[9];
    const float* br   = (const float*)d_in[10];
    const float* wq   = (const float*)d_in[11];
    const float* bq   = (const float*)d_in[12];
    const float* w1   = (const float*)d_in[13];
    const float* g1s  = (const float*)d_in[14];
    const float* g1b  = (const float*)d_in[15];
    const float* w2   = (const float*)d_in[16];
    const float* g2s  = (const float*)d_in[17];
    const float* g2b  = (const float*)d_in[18];
    const float* whd  = (const float*)d_in[19];
    const float* bhd  = (const float*)d_in[20];
    const float* whx  = (const float*)d_in[21];
    const float* bhx  = (const float*)d_in[22];
    const float* why  = (const float*)d_in[23];
    const float* bhy  = (const float*)d_in[24];
    const float* whc  = (const float*)d_in[25];
    const float* bhc  = (const float*)d_in[26];
    float* out = (float*)d_out;

    float *hctx, *z, *r, *hnew, *ta, *tb, *tc;
    float2 *wzr, *wqp, *wt1, *wt2;
    cudaGetSymbolAddress((void**)&hctx, g_hctx);
    cudaGetSymbolAddress((void**)&z,    g_z);
    cudaGetSymbolAddress((void**)&r,    g_r);
    cudaGetSymbolAddress((void**)&hnew, g_hnew);
    cudaGetSymbolAddress((void**)&ta,   g_ta);
    cudaGetSymbolAddress((void**)&tb,   g_tb);
    cudaGetSymbolAddress((void**)&tc,   g_tc);
    cudaGetSymbolAddress((void**)&wzr,  g_wzr);
    cudaGetSymbolAddress((void**)&wqp,  g_wq);
    cudaGetSymbolAddress((void**)&wt1,  g_wt1);
    cudaGetSymbolAddress((void**)&wt2,  g_wt2);

    const int SM_I = 2*(8*3*264)*4;     // 50688 bytes (2 input stages)

    cudaFuncSetAttribute(conv3x3_cp_k<GRU_IN,128,512,4,-1>,
                         cudaFuncAttributeMaxDynamicSharedMemorySize, SM_I);
    cudaFuncSetAttribute(conv3x3_cp_k<GRU_IN,64,256,2,-1>,
                         cudaFuncAttributeMaxDynamicSharedMemorySize, SM_I);
    cudaFuncSetAttribute(conv3x3_cp_k<TC,HID,256,0,0>,
                         cudaFuncAttributeMaxDynamicSharedMemorySize, SM_I);
    cudaFuncSetAttribute(conv3x3_cp_k<HID,HID,256,0,1>,
                         cudaFuncAttributeMaxDynamicSharedMemorySize, SM_I);

    // One-time weight permutes + gnsum zero (single launch)
    {
        int total = NZR + NQ + NT1 + NT2;
        wperm_all_k<<<(total+255)/256, 256>>>(wz, wr, wq, w1, w2);
    }

    dim3 cgrid(Hc, Bn);

    build_hctx_k<<<(4*NPIX)/256, 256>>>(d_, sx, sy, conf, fL, fR);

    // fused z|r conv: z = sigmoid(conv_z); r*feat = sigmoid(conv_r)*feat
    conv3x3_cp_k<GRU_IN,128,512,4,-1><<<cgrid, 512, SM_I>>>(
        feat, 64, fL, 64, hctx, HCTX,
        wzr, bz, br, z, nullptr, feat, r);

    // q conv + GRU combine -> hnew (and output h slot)
    conv3x3_cp_k<GRU_IN,64,256,2,-1><<<cgrid, 256, SM_I>>>(
        r, 64, fL, 64, hctx, HCTX,
        wqp, bq, nullptr, hnew, z, feat, out + O_H);

    // trunk1: conv(hnew) -> ta, with fused GN set-0 stats in epilogue
    conv3x3_cp_k<TC,HID,256,0,0><<<cgrid, 256, SM_I>>>(
        hnew, TC, hnew, TC, hnew, TC,
        wt1, nullptr, nullptr, ta, nullptr, nullptr, nullptr);

    // gn1 apply + SiLU: ta -> tb
    gn_apply_k<<<(Bn*HID*HW)/4/256, 256>>>(ta, tb, g1s, g1b, 0);

    // trunk2: conv(tb) -> tc, with fused GN set-1 stats in epilogue
    conv3x3_cp_k<HID,HID,256,0,1><<<cgrid, 256, SM_I>>>(
        tb, HID, tb, HID, tb, HID,
        wt2, nullptr, nullptr, tc, nullptr, nullptr, nullptr);

    // heads with fused GN2 apply + SiLU
    heads_k<<<NPIX/256, 256>>>(tc, g2s, g2b, d_, sx, sy, conf,
                               whd, bhd, whx, bhx, why, bhy, whc, bhc, out);
}

// round 14
// speedup vs baseline: 1.0617x; 1.0545x over previous
#include <cuda_runtime.h>
#include <cuda_bf16.h>
#include <math.h>
#include <stdint.h>

// Problem constants
#define Bn 4
#define FC 64
#define TC 64
#define HID 48
#define HR 2
#define Gg 8
#define Hc 128
#define Wc 256
#define Dd 5
#define CG 8
#define GRU_IN 236
#define HCTX 108
#define HW (Hc*Wc)            // 32768
#define NPIX (Bn*HW)          // 131072

// Output layout (flattened tuple in return order)
#define O_D    0
#define O_SX   (NPIX)
#define O_SY   (2*NPIX)
#define O_H    (3*NPIX)
#define O_CONF (3*NPIX + Bn*TC*HW)

// Scratch (device globals; no allocation allowed)
__device__ float g_hctx[(size_t)Bn*HCTX*HW];     // [fR_w(64), d,sx,sy,conf(4), cost(40)]
__device__ float g_z  [(size_t)Bn*TC*HW];
__device__ float g_r  [(size_t)Bn*TC*HW];        // holds r*feat (fused)
__device__ float g_hnew[(size_t)Bn*TC*HW];
__device__ float g_ta [(size_t)Bn*HID*HW];       // trunk1 raw output
__device__ float g_tb [(size_t)Bn*HID*HW];       // gn1(ta)
__device__ float g_tc [(size_t)Bn*HID*HW];       // trunk2 raw output
__device__ float g_gnsum[128];                   // 2 sets x 32 (b,g) x {sum,sum2}

// Fragment-permuted tf32 weights: [chunk][tap][ocq][lane] -> float2 {b0,b1}
__device__ float2 g_wzr[30*9*16*32];   // z|r fused, OC=128
__device__ float2 g_wq [30*9* 8*32];   // q, OC=64
__device__ float2 g_wt1[ 8*9* 6*32];   // trunk1, IC=64, OC=48
__device__ float2 g_wt2[ 6*9* 6*32];   // trunk2, IC=48, OC=48

#define GN_N ((HID/Gg)*HW)     // elements per (b,group) = 196608

// ---- fast transcendentals (MUFU-based) ----
__device__ __forceinline__ float fsig(float x){
    return __fdividef(1.0f, 1.0f + __expf(-x));
}
__device__ __forceinline__ float ftanh(float x){
    float xc = fminf(fmaxf(x, -15.0f), 15.0f);
    float e  = __expf(2.0f*xc);
    return __fdividef(e - 1.0f, e + 1.0f);
}
__device__ __forceinline__ float fsoftplus(float x){
    return (x > 20.0f) ? x : __logf(1.0f + __expf(x));
}

__device__ __forceinline__ unsigned to_tf32(float v) {
    unsigned u;
    asm("cvt.rna.tf32.f32 %0, %1;" : "=r"(u) : "f"(v));
    return u;
}

__device__ __forceinline__ void mma_tf32(float* c, unsigned a0, unsigned a1,
                                         unsigned a2, unsigned a3,
                                         unsigned b0, unsigned b1) {
    asm volatile(
        "mma.sync.aligned.m16n8k8.row.col.f32.tf32.tf32.f32 "
        "{%0,%1,%2,%3}, {%4,%5,%6,%7}, {%8,%9}, {%0,%1,%2,%3};"
        : "+f"(c[0]), "+f"(c[1]), "+f"(c[2]), "+f"(c[3])
        : "r"(a0), "r"(a1), "r"(a2), "r"(a3), "r"(b0), "r"(b1));
}

__device__ __forceinline__ void cp16(uint32_t dst, const void* src, int szbytes){
    asm volatile("cp.async.cg.shared.global [%0], [%1], 16, %2;"
                 :: "r"(dst), "l"(src), "r"(szbytes));
}
__device__ __forceinline__ void cp_commit(){ asm volatile("cp.async.commit_group;"); }
__device__ __forceinline__ void cp_wait_all(){ asm volatile("cp.async.wait_all;" ::: "memory"); }

__device__ __forceinline__ void gn_mr(int set, int bg, float& mean, float& rstd)
{
    float s  = g_gnsum[set*64 + bg*2];
    float s2 = g_gnsum[set*64 + bg*2 + 1];
    mean = s * (1.0f/(float)GN_N);
    float var = s2 * (1.0f/(float)GN_N) - mean*mean;
    rstd = rsqrtf(var + 1e-5f);
}

// ---------------------------------------------------------------------------
// K0: ALL weight permutes in one launch + zero gn accumulator.
// ---------------------------------------------------------------------------
__device__ __forceinline__ void wperm_one(const float* wA, const float* wB,
                                          float2* dst, int IC, int OC, int i)
{
    int lane = i & 31;
    int t1   = i >> 5;
    int ocq  = t1 % (OC/8);
    int rest = t1 / (OC/8);
    int tap  = rest % 9;
    int chunk= rest / 9;
    int gID = lane >> 2, tig = lane & 3;
    int oc  = ocq*8 + gID;
    int ic0 = chunk*8 + tig, ic1 = ic0 + 4;
    const float* wsrc = wA; int oce = oc;
    if (oc >= 64 && wB) { wsrc = wB; oce = oc - 64; }
    float v0 = (ic0 < IC) ? wsrc[((size_t)oce*IC + ic0)*9 + tap] : 0.f;
    float v1 = (ic1 < IC) ? wsrc[((size_t)oce*IC + ic1)*9 + tap] : 0.f;
    dst[i] = make_float2(__uint_as_float(to_tf32(v0)), __uint_as_float(to_tf32(v1)));
}

#define NZR (30*9*16*32)
#define NQ  (30*9*8*32)
#define NT1 (8*9*6*32)
#define NT2 (6*9*6*32)

__global__ void wperm_all_k(const float* __restrict__ wz, const float* __restrict__ wr,
                            const float* __restrict__ wq, const float* __restrict__ w1,
                            const float* __restrict__ w2)
{
    int i = blockIdx.x*blockDim.x + threadIdx.x;
    if (i < 128) g_gnsum[i] = 0.f;
    if (i < NZR) { wperm_one(wz, wr, g_wzr, GRU_IN, 128, i); return; }
    i -= NZR;
    if (i < NQ)  { wperm_one(wq, nullptr, g_wq, GRU_IN, 64, i); return; }
    i -= NQ;
    if (i < NT1) { wperm_one(w1, nullptr, g_wt1, TC, HID, i); return; }
    i -= NT1;
    if (i < NT2) { wperm_one(w2, nullptr, g_wt2, HID, HID, i); return; }
}

// ---------------------------------------------------------------------------
// K1: build hctx108 = [fR_w(64), d, sx, sy, conf, cost(40)]
// 4 threads per pixel; window-gather: the 5 offsets are consecutive ints, so
// all taps live in a 6-float window with ONE shared fractional weight.
// Border clamping of both window endpoints reproduces 'border' padding exactly.
// ---------------------------------------------------------------------------
__global__ void build_hctx_k(const float* __restrict__ d_, const float* __restrict__ sx,
                             const float* __restrict__ sy, const float* __restrict__ conf,
                             const float* __restrict__ fL, const float* __restrict__ fR)
{
    int idx = blockIdx.x*blockDim.x + threadIdx.x;
    if (idx >= 4*NPIX) return;
    int quarter = idx & 3;
    int pixi = idx >> 2;
    int w = pixi & (Wc-1);
    int h = (pixi >> 8) & (Hc-1);
    int b = pixi >> 15;
    size_t p = (size_t)h*Wc + w;
    size_t pix = (size_t)pixi;

    float d0 = d_[pix];

    // window setup: xs_o = (w - d0) + 2 - o, o = 0..4
    float xw = (float)w - d0;
    float fb = floorf(xw);
    int   ib = (int)fb;
    float fr = xw - fb;          // shared fractional weight
    float fr1 = 1.0f - fr;
    int jidx[6];
#pragma unroll
    for (int j = 0; j < 6; j++) jidx[j] = min(max(ib - 2 + j, 0), Wc-1);

    size_t hb = (size_t)b * HCTX * HW;
    float cost[Dd] = {0.f,0.f,0.f,0.f,0.f};

    int c0 = quarter*16;
    for (int c = c0; c < c0+16; c++) {
        size_t fbase = ((size_t)(b*FC + c)) * HW;
        float fl = __ldg(fL + fbase + p);
        const float* fRrow = fR + fbase + (size_t)h*Wc;
        float v[6];
#pragma unroll
        for (int j = 0; j < 6; j++) v[j] = __ldg(fRrow + jidx[j]);
#pragma unroll
        for (int o = 0; o < Dd; o++) {
            // taps at window slots (4-o, 5-o)
            float s = v[4-o]*fr1 + v[5-o]*fr;
            cost[o] += fl * s;
            if (o == HR) g_hctx[hb + (size_t)c*HW + p] = s;   // fR_w
        }
        if ((c & (CG-1)) == (CG-1)) {
            int g = c >> 3;
#pragma unroll
            for (int o = 0; o < Dd; o++) {
                g_hctx[hb + (size_t)(68 + g*Dd + o)*HW + p] = cost[o] * (1.0f/(float)CG);
                cost[o] = 0.f;
            }
        }
    }
    if (quarter == 0) {
        g_hctx[hb + (size_t)64*HW + p] = d0;
        g_hctx[hb + (size_t)65*HW + p] = sx[pix];
        g_hctx[hb + (size_t)66*HW + p] = sy[pix];
        g_hctx[hb + (size_t)67*HW + p] = conf[pix];
    }
}

// ---------------------------------------------------------------------------
// Tensor-core 3x3 conv (pad=1), implicit GEMM, tf32 mma.
// Inputs cp.async double-buffered in smem; weights read as pre-permuted
// fragments directly from global (L1/L2-resident, coalesced float2).
// MODE 0: plain   MODE 2: GRU combine (q)   MODE 4: fused z|r (OC=128)
// ---------------------------------------------------------------------------
template<int IC, int OC, int THREADS, int MODE>
__global__ void __launch_bounds__(THREADS, (THREADS==512)?1:2)
conv3x3_cp_k(const float* __restrict__ p0, int C0tot,
             const float* __restrict__ p1, int C1tot,
             const float* __restrict__ p2, int C2tot,
             const float2* __restrict__ wperm,
             const float* __restrict__ biasA, const float* __restrict__ biasB,
             float* __restrict__ out,
             const float* __restrict__ zbuf, const float* __restrict__ featbuf,
             float* __restrict__ out2)
{
    constexpr int NW   = THREADS/32;
    constexpr int OCW  = OC/(NW/4);
    constexpr int NF   = OCW/8;
    constexpr int OC8  = OC/8;
    constexpr int NCHK = (IC + 7)/8;
    constexpr int PI   = 264;            // ism row pitch (words)
    constexpr int IST  = 8*3*PI;         // ism words per stage

    extern __shared__ unsigned dsm[];
    uint32_t smem_b = (uint32_t)__cvta_generic_to_shared(dsm);

    const int tid  = threadIdx.x;
    const int lane = tid & 31;
    const int warp = tid >> 5;
    const int wm   = warp & 3;
    const int wn   = warp >> 2;
    const int h    = blockIdx.x;
    const int b    = blockIdx.y;
    const int gID  = lane >> 2;
    const int tig  = lane & 3;

    float acc[4][NF][4];
#pragma unroll
    for (int mf = 0; mf < 4; mf++)
#pragma unroll
        for (int f = 0; f < NF; f++)
#pragma unroll
            for (int j = 0; j < 4; j++) acc[mf][f][j] = 0.f;

    auto stage = [&](int chunk, int s) {
        for (int t = warp; t < 24; t += NW) {
            int icl = t / 3;
            int ky  = t - icl*3;
            int ic  = chunk*8 + icl;
            int gy  = h - 1 + ky;
            bool valid = (ic < IC) && (gy >= 0) && (gy < Hc);
            int icc = valid ? ic : 0;
            int gyc = min(max(gy, 0), Hc-1);
            const float* srcrow;
            if (icc < 64)       srcrow = p0 + (((size_t)b*C0tot + icc)*Hc + gyc)*Wc;
            else if (icc < 128) srcrow = p1 + (((size_t)b*C1tot + (icc-64))*Hc + gyc)*Wc;
            else                srcrow = p2 + (((size_t)b*C2tot + (icc-128))*Hc + gyc)*Wc;
            uint32_t dstw = smem_b + ((uint32_t)(s*IST + t*PI))*4u;
            int sz = valid ? 16 : 0;
            cp16(dstw + (4u + (uint32_t)lane*4u)*4u,      srcrow + lane*4,      sz);
            cp16(dstw + (4u + (uint32_t)(lane+32)*4u)*4u, srcrow + (lane+32)*4, sz);
            if (lane == 0) dsm[s*IST + t*PI + 3]   = 0u;   // left pad
            if (lane == 1) dsm[s*IST + t*PI + 260] = 0u;   // right pad
        }
    };

    stage(0, 0);
    cp_commit();

    for (int c = 0; c < NCHK; c++) {
        cp_wait_all();
        __syncthreads();
        if (c + 1 < NCHK) { stage(c+1, (c+1)&1); cp_commit(); }

        const unsigned* isb = dsm + (c&1)*IST;
        const float2* wcb = wperm + ((size_t)(c*9)*OC8)*32;

#pragma unroll
        for (int tap = 0; tap < 9; tap++) {
            const int ky = tap/3, kx = tap - (tap/3)*3;
            const float2* wtb = wcb + ((size_t)tap*OC8 + wn*NF)*32 + lane;
            unsigned b0[NF], b1[NF];
#pragma unroll
            for (int f = 0; f < NF; f++) {
                float2 wv = __ldg(wtb + f*32);
                b0[f] = __float_as_uint(wv.x);
                b1[f] = __float_as_uint(wv.y);
            }
            const unsigned* ib = isb + ky*PI + kx + 3;
#pragma unroll
            for (int mf = 0; mf < 4; mf++) {
                int p = wm*64 + mf*16 + gID;
                unsigned a0 = ib[ tig   *3*PI + p];
                unsigned a1 = ib[ tig   *3*PI + p + 8];
                unsigned a2 = ib[(tig+4)*3*PI + p];
                unsigned a3 = ib[(tig+4)*3*PI + p + 8];
#pragma unroll
                for (int f = 0; f < NF; f++)
                    mma_tf32(acc[mf][f], a0, a1, a2, a3, b0[f], b1[f]);
            }
        }
    }

    // ---- epilogue ----
#pragma unroll
    for (int mf = 0; mf < 4; mf++) {
#pragma unroll
        for (int f = 0; f < NF; f++) {
            int px0 = wm*64 + mf*16 + gID;
            int oc0 = wn*OCW + f*8 + 2*tig;
#pragma unroll
            for (int e = 0; e < 4; e++) {
                int px = px0 + (e >> 1)*8;
                int oc = oc0 + (e & 1);
                float val = acc[mf][f][e];
                if (MODE == 4) {
                    if (oc < 64) {
                        size_t o = (((size_t)b*64 + oc)*Hc + h)*Wc + px;
                        out[o] = fsig(val + biasA[oc]);
                    } else {
                        int oc2 = oc - 64;
                        size_t o = (((size_t)b*64 + oc2)*Hc + h)*Wc + px;
                        out2[o] = fsig(val + biasB[oc2]) * featbuf[o];
                    }
                } else {
                    size_t o = (((size_t)b*OC + oc)*Hc + h)*Wc + px;
                    if (MODE == 0) {
                        out[o] = val + (biasA ? biasA[oc] : 0.f);
                    } else { // MODE 2: GRU combine
                        float q = ftanh(val + biasA[oc]);
                        float z = zbuf[o];
                        float fv = featbuf[o];
                        float hn = (1.0f - z)*fv + z*q;
                        out[o]  = hn;
                        out2[o] = hn;
                    }
                }
            }
        }
    }
}

// ---------------------------------------------------------------------------
// GroupNorm partial stats: 256 blocks = (b,group) x 8 slices; atomicAdd sums.
// ---------------------------------------------------------------------------
__global__ void gn_statsp_k(const float* __restrict__ x, int set)
{
    __shared__ float ss[256], ss2[256];
    int bg    = blockIdx.x >> 3;
    int slice = blockIdx.x & 7;
    int b  = bg >> 3, g = bg & 7;
    size_t base = ((size_t)b*HID + g*(HID/Gg)) * HW + (size_t)slice*(GN_N/8);
    const int N4 = (GN_N/8)/4;   // 6144 float4 per slice
    const float4* x4 = (const float4*)(x + base);
    float s = 0.f, s2 = 0.f;
    for (int i = threadIdx.x; i < N4; i += 256) {
        float4 v = x4[i];
        s  += v.x + v.y + v.z + v.w;
        s2 += v.x*v.x + v.y*v.y + v.z*v.z + v.w*v.w;
    }
    ss[threadIdx.x] = s; ss2[threadIdx.x] = s2;
    __syncthreads();
    for (int off = 128; off > 0; off >>= 1) {
        if (threadIdx.x < off) {
            ss[threadIdx.x]  += ss[threadIdx.x + off];
            ss2[threadIdx.x] += ss2[threadIdx.x + off];
        }
        __syncthreads();
    }
    if (threadIdx.x == 0) {
        atomicAdd(&g_gnsum[set*64 + bg*2],     ss[0]);
        atomicAdd(&g_gnsum[set*64 + bg*2 + 1], ss2[0]);
    }
}

// ---------------------------------------------------------------------------
// GroupNorm apply + SiLU (float4)
// ---------------------------------------------------------------------------
__global__ void gn_apply_k(const float* __restrict__ x, float* __restrict__ y,
                           const float* __restrict__ scale, const float* __restrict__ bias,
                           int set)
{
    int i4 = blockIdx.x*blockDim.x + threadIdx.x;
    const int n4 = (Bn*HID*HW)/4;
    if (i4 >= n4) return;
    int i = i4*4;
    int c = (i / HW) % HID;
    int b = i / (HID*HW);
    int grp = c / (HID/Gg);
    float mean, rstd;
    gn_mr(set, b*8+grp, mean, rstd);
    float sc = scale[c]*rstd, bi = bias[c] - mean*rstd*scale[c];
    float4 v = ((const float4*)x)[i4];
    float4 o;
    float t;
    t = v.x*sc + bi; o.x = t * fsig(t);
    t = v.y*sc + bi; o.y = t * fsig(t);
    t = v.z*sc + bi; o.z = t * fsig(t);
    t = v.w*sc + bi; o.w = t * fsig(t);
    ((float4*)y)[i4] = o;
}

// ---------------------------------------------------------------------------
// Heads: fused GN2-apply + SiLU + four 1x1 convs (48->1) + activations.
// ---------------------------------------------------------------------------
__global__ void heads_k(const float* __restrict__ t,
                        const float* __restrict__ gnsc, const float* __restrict__ gnbi,
                        const float* __restrict__ d_, const float* __restrict__ sx,
                        const float* __restrict__ sy, const float* __restrict__ conf,
                        const float* __restrict__ wd,  const float* __restrict__ bd,
                        const float* __restrict__ wsx, const float* __restrict__ bsx,
                        const float* __restrict__ wsy, const float* __restrict__ bsy,
                        const float* __restrict__ wcf, const float* __restrict__ bcf,
                        float* __restrict__ out)
{
    __shared__ float wsm[4][HID];
    __shared__ float csc[HID], cbi[HID];
    int tid = threadIdx.x;
    if (tid < HID)              wsm[0][tid]        = wd [tid];
    else if (tid < 2*HID)       wsm[1][tid-HID]    = wsx[tid-HID];
    else if (tid < 3*HID)       wsm[2][tid-2*HID]  = wsy[tid-2*HID];
    else if (tid < 4*HID)       wsm[3][tid-3*HID]  = wcf[tid-3*HID];
    if (tid < HID) { csc[tid] = gnsc[tid]; cbi[tid] = gnbi[tid]; }
    __syncthreads();

    int idx = blockIdx.x*blockDim.x + tid;
    if (idx >= NPIX) return;
    int b = idx >> 15;
    size_t p = (size_t)(idx & (HW-1));
    size_t pix = (size_t)idx;

    float gmean[8], grstd[8];
#pragma unroll
    for (int g = 0; g < 8; g++) gn_mr(1, b*8+g, gmean[g], grstd[g]);

    float a0=0.f, a1=0.f, a2=0.f, a3=0.f;
    size_t base = (size_t)b*HID*HW + p;
#pragma unroll
    for (int c = 0; c < HID; c++) {
        int g = c / (HID/Gg);
        float v = (t[base + (size_t)c*HW] - gmean[g])*grstd[g]*csc[c] + cbi[c];
        v = v * fsig(v);
        a0 = fmaf(v, wsm[0][c], a0);
        a1 = fmaf(v, wsm[1][c], a1);
        a2 = fmaf(v, wsm[2][c], a2);
        a3 = fmaf(v, wsm[3][c], a3);
    }
    float ad = a0 + bd[0] + d_[pix];
    out[O_D + pix]  = fsoftplus(ad);
    out[O_SX + pix] = sx[pix] + (a1 + bsx[0]) * 0.1f;
    out[O_SY + pix] = sy[pix] + (a2 + bsy[0]) * 0.1f;
    out[O_CONF + pix] = fsig(a3 + bcf[0] + 2.0f*conf[pix] - 1.0f);
}

// ---------------------------------------------------------------------------
extern "C" void kernel_launch(void* const* d_in, const int* in_sizes, int n_in,
                              void* d_out, int out_size)
{
    const float* d_   = (const float*)d_in[0];
    const float* sx   = (const float*)d_in[1];
    const float* sy   = (const float*)d_in[2];
    const float* conf = (const float*)d_in[3];
    const float* feat = (const float*)d_in[4];
    const float* fL   = (const float*)d_in[5];
    const float* fR   = (const float*)d_in[6];
    const float* wz   = (const float*)d_in[7];
    const float* bz   = (const float*)d_in[8];
    const float* wr   = (const float*)d_in[9];
    const float* br   = (const float*)d_in[10];
    const float* wq   = (const float*)d_in[11];
    const float* bq   = (const float*)d_in[12];
    const float* w1   = (const float*)d_in[13];
    const float* g1s  = (const float*)d_in[14];
    const float* g1b  = (const float*)d_in[15];
    const float* w2   = (const float*)d_in[16];
    const float* g2s  = (const float*)d_in[17];
    const float* g2b  = (const float*)d_in[18];
    const float* whd  = (const float*)d_in[19];
    const float* bhd  = (const float*)d_in[20];
    const float* whx  = (const float*)d_in[21];
    const float* bhx  = (const float*)d_in[22];
    const float* why  = (const float*)d_in[23];
    const float* bhy  = (const float*)d_in[24];
    const float* whc  = (const float*)d_in[25];
    const float* bhc  = (const float*)d_in[26];
    float* out = (float*)d_out;

    float *hctx, *z, *r, *hnew, *ta, *tb, *tc;
    float2 *wzr, *wqp, *wt1, *wt2;
    cudaGetSymbolAddress((void**)&hctx, g_hctx);
    cudaGetSymbolAddress((void**)&z,    g_z);
    cudaGetSymbolAddress((void**)&r,    g_r);
    cudaGetSymbolAddress((void**)&hnew, g_hnew);
    cudaGetSymbolAddress((void**)&ta,   g_ta);
    cudaGetSymbolAddress((void**)&tb,   g_tb);
    cudaGetSymbolAddress((void**)&tc,   g_tc);
    cudaGetSymbolAddress((void**)&wzr,  g_wzr);
    cudaGetSymbolAddress((void**)&wqp,  g_wq);
    cudaGetSymbolAddress((void**)&wt1,  g_wt1);
    cudaGetSymbolAddress((void**)&wt2,  g_wt2);

    const int SM_I = 2*(8*3*264)*4;     // 50688 bytes (2 input stages)

    cudaFuncSetAttribute(conv3x3_cp_k<GRU_IN,128,512,4>,
                         cudaFuncAttributeMaxDynamicSharedMemorySize, SM_I);
    cudaFuncSetAttribute(conv3x3_cp_k<GRU_IN,64,256,2>,
                         cudaFuncAttributeMaxDynamicSharedMemorySize, SM_I);
    cudaFuncSetAttribute(conv3x3_cp_k<TC,HID,256,0>,
                         cudaFuncAttributeMaxDynamicSharedMemorySize, SM_I);
    cudaFuncSetAttribute(conv3x3_cp_k<HID,HID,256,0>,
                         cudaFuncAttributeMaxDynamicSharedMemorySize, SM_I);

    // One-time weight permutes + gnsum zero (single launch)
    {
        int total = NZR + NQ + NT1 + NT2;
        wperm_all_k<<<(total+255)/256, 256>>>(wz, wr, wq, w1, w2);
    }

    dim3 cgrid(Hc, Bn);

    build_hctx_k<<<(4*NPIX)/256, 256>>>(d_, sx, sy, conf, fL, fR);

    // fused z|r conv: z = sigmoid(conv_z); r*feat = sigmoid(conv_r)*feat
    conv3x3_cp_k<GRU_IN,128,512,4><<<cgrid, 512, SM_I>>>(
        feat, 64, fL, 64, hctx, HCTX,
        wzr, bz, br, z, nullptr, feat, r);

    // q conv + GRU combine -> hnew (and output h slot)
    conv3x3_cp_k<GRU_IN,64,256,2><<<cgrid, 256, SM_I>>>(
        r, 64, fL, 64, hctx, HCTX,
        wqp, bq, nullptr, hnew, z, feat, out + O_H);

    // trunk1: conv(hnew) -> ta
    conv3x3_cp_k<TC,HID,256,0><<<cgrid, 256, SM_I>>>(
        hnew, TC, hnew, TC, hnew, TC,
        wt1, nullptr, nullptr, ta, nullptr, nullptr, nullptr);
    gn_statsp_k<<<256, 256>>>(ta, 0);
    gn_apply_k<<<(Bn*HID*HW)/4/256, 256>>>(ta, tb, g1s, g1b, 0);

    // trunk2: conv(tb) -> tc
    conv3x3_cp_k<HID,HID,256,0><<<cgrid, 256, SM_I>>>(
        tb, HID, tb, HID, tb, HID,
        wt2, nullptr, nullptr, tc, nullptr, nullptr, nullptr);
    gn_statsp_k<<<256, 256>>>(tc, 1);

    // heads with fused GN2 apply + SiLU
    heads_k<<<NPIX/256, 256>>>(tc, g2s, g2b, d_, sx, sy, conf,
                               whd, bhd, whx, bhx, why, bhy, whc, bhc, out);
}